// round 15
// baseline (speedup 1.0000x reference)
#include <cuda_runtime.h>

// Double-softmax attention, fp32. B=4,H=8,N=2048,D=64.
//   L = Q K^T * scale ; mask = softmax(2L) ; attn = softmax(L*mask) ; O = attn V
// One CTA = 16 query rows of one (b,h), 256 threads, warp-local staging.
// P1: register-prefetched 256-key K chunks, t = L*exp(2L), Z1 folded.
// S panel: S2[qpair][key][2], pitch 4100 floats.
// P3: O = P V with the exp2 convert of group g+1 INTERLEAVED into the MMA
//     loop of group g (disjoint S regions; one syncwarp per group).

#define NKEYS   2048
#define DIM     64
#define MQ      16
#define CHUNK   256
#define NCHUNK  8
#define THREADS 256
#define NBLK_Q  128

#define PITCH2    4100                 // S2 row pitch in floats (16B bank stagger)
#define PITCHF4   (PITCH2 / 4)         // 1025
#define S_FLOATS  (8 * PITCH2)         // 32800
#define KT_FLOATS (CHUNK * DIM)        // 16384 (K tile; P3 scratch 16 segs)
#define QS_FLOATS (MQ * DIM)           // 1024
#define SMEM_FLOATS (S_FLOATS + KT_FLOATS + QS_FLOATS + 128 + 16 + 128)
#define SMEM_BYTES  (SMEM_FLOATS * 4)  // ~202 KB

typedef unsigned long long u64;

__device__ __forceinline__ u64 pk2(float lo, float hi) {
    u64 r; asm("mov.b64 %0,{%1,%2};" : "=l"(r) : "f"(lo), "f"(hi)); return r;
}
__device__ __forceinline__ void upk2(u64 a, float& lo, float& hi) {
    asm("mov.b64 {%0,%1},%2;" : "=f"(lo), "=f"(hi) : "l"(a));
}
__device__ __forceinline__ void ffma2(u64& d, u64 a, u64 b) {
    asm("fma.rn.f32x2 %0,%1,%2,%0;" : "+l"(d) : "l"(a), "l"(b));
}
__device__ __forceinline__ float ex2f(float x) {
    float r; asm("ex2.approx.f32 %0,%1;" : "=f"(r) : "f"(x)); return r;
}

__global__ __launch_bounds__(THREADS, 1)
void dsmax_attn_kernel(const float* __restrict__ Q,
                       const float* __restrict__ K,
                       const float* __restrict__ V,
                       const float* __restrict__ scalep,
                       float* __restrict__ O)
{
    extern __shared__ float smem[];
    float* S     = smem;                      // S2: [8 qp][PITCH2]  t -> P'
    float* Kt    = S + S_FLOATS;              // [CHUNK][DIM] swizzled K / P3 scratch
    float* Qs    = Kt + KT_FLOATS;            // [MQ][DIM] swizzled Q
    float* zscr  = Qs + QS_FLOATS;            // [8 warps][16 rows] Z1 partials
    float* c2s   = zscr + 128;                // [16] log2e / Z1
    float* zscr2 = c2s + 16;                  // [8 warps][16 rows] Z2 partials

    const int tid  = threadIdx.x;
    const int warp = tid >> 5, lane = tid & 31;
    const int bh   = blockIdx.x >> 7;
    const int qb   = (blockIdx.x & (NBLK_Q - 1)) * MQ;
    const float scale = *scalep;

    const float* Qb = Q + ((size_t)bh * NKEYS + qb) * DIM;
    const float* Kb = K + (size_t)bh * NKEYS * DIM;
    const float* Vb = V + (size_t)bh * NKEYS * DIM;
    float*       Ob = O + ((size_t)bh * NKEYS + qb) * DIM;

    // ---- stage Q swizzled: col16 = d4 ^ ((q>>2)&3) ----
    {
        const int q = tid >> 4, d4 = tid & 15;
        *(float4*)&Qs[q * DIM + ((d4 ^ ((q >> 2) & 3)) << 2)] = ((const float4*)Qb)[tid];
    }

    // ---- warp-local K prefetch: warp w owns keys [32w, 32w+32) of each chunk ----
    float4 pf[16];
    const int lhi = lane >> 4;          // key parity within pair
    const int ld4 = lane & 15;          // float4 column within key row
#define LDGK(C)                                                               \
    {                                                                         \
        const float4* src = (const float4*)(Kb + (size_t)(C) * CHUNK * DIM);  \
        _Pragma("unroll")                                                     \
        for (int i = 0; i < 16; i++)                                          \
            pf[i] = src[(size_t)(32 * warp + 2 * i + lhi) * 16 + ld4];        \
    }
    LDGK(0);
    __syncthreads();   // Qs visible to everyone

    // ================= Phase 1: t = L*exp(2L), Z1 partials =================
    // Thread keys: {32w + l7 + 8j, j=0..3}; rows 4qg..4qg+3.
    const int l7 = lane & 7;
    const int qg = (lane >> 3) & 3;
    float z1p[4] = {0.f, 0.f, 0.f, 0.f};

    for (int c = 0; c < NCHUNK; c++) {
        // commit own slice, swizzle col16 = ld4 ^ (key & 7)
        #pragma unroll
        for (int i = 0; i < 16; i++) {
            const int key = 32 * warp + 2 * i + lhi;
            *(float4*)&Kt[key * DIM + ((ld4 ^ ((2 * i + lhi) & 7)) << 2)] = pf[i];
        }
        __syncwarp();                 // slice visible to own warp
        if (c + 1 < NCHUNK) LDGK(c + 1);

        u64 acc[4][4];   // [jq][j]
        #pragma unroll
        for (int a = 0; a < 4; a++)
            #pragma unroll
            for (int b = 0; b < 4; b++) acc[a][b] = 0ull;

        const float* kr0 = Kt + (32 * warp + l7) * DIM;
        #pragma unroll
        for (int d4 = 0; d4 < 16; d4++) {
            const int kco = (d4 ^ l7) << 2;
            ulonglong2 kv[4];
            #pragma unroll
            for (int j = 0; j < 4; j++)
                kv[j] = *(const ulonglong2*)(kr0 + (8 * j) * DIM + kco);
            const int qco = (d4 ^ qg) << 2;
            #pragma unroll
            for (int jq = 0; jq < 4; jq++) {
                ulonglong2 qv = *(const ulonglong2*)(Qs + (4 * qg + jq) * DIM + qco);
                #pragma unroll
                for (int j = 0; j < 4; j++) {
                    ffma2(acc[jq][j], qv.x, kv[j].x);
                    ffma2(acc[jq][j], qv.y, kv[j].y);
                }
            }
        }

        // epilogue: t = L*exp(2L); q-pair float2s into S2
        float tmat[4][4];
        #pragma unroll
        for (int jq = 0; jq < 4; jq++) {
            #pragma unroll
            for (int j = 0; j < 4; j++) {
                float lo, hi; upk2(acc[jq][j], lo, hi);
                float L  = (lo + hi) * scale;
                float e2 = __expf(2.0f * L);
                z1p[jq] += e2;
                tmat[jq][j] = L * e2;
            }
        }
        #pragma unroll
        for (int p01 = 0; p01 < 2; p01++) {
            const int qp = 2 * qg + p01;
            #pragma unroll
            for (int j = 0; j < 4; j++) {
                const int gk = c * CHUNK + 32 * warp + l7 + 8 * j;
                *(float2*)&S[(size_t)qp * PITCH2 + gk * 2] =
                    make_float2(tmat[2 * p01][j], tmat[2 * p01 + 1][j]);
            }
        }
        __syncwarp();                 // own warp done reading slice before next commit
    }

    // ---- Z1 reduce: over the 8 l7 lanes, then across warps ----
    #pragma unroll
    for (int jq = 0; jq < 4; jq++) {
        float v = z1p[jq];
        v += __shfl_xor_sync(0xffffffffu, v, 1);
        v += __shfl_xor_sync(0xffffffffu, v, 2);
        v += __shfl_xor_sync(0xffffffffu, v, 4);
        if (l7 == 0) zscr[warp * 16 + qg * 4 + jq] = v;   // slot == row q
    }
    __syncthreads();
    if (tid < 16) {
        float z1 = 0.f;
        #pragma unroll
        for (int w = 0; w < 8; w++) z1 += zscr[w * 16 + tid];
        c2s[tid] = 1.4426950408889634f / z1;      // log2e / Z1
    }
    __syncthreads();

    // ================= Phase 3: warp-local convert + O = P' V =================
    // Warp w owns stripe keys [256w, +256). Lanes: 16 d-lanes x 2 key-halves.
    const int dlane = lane & 15;
    const int kh    = lane >> 4;
    const int sk    = warp * 256;
    const int wb128 = warp * 128;               // stripe base in f4 units per qp row

    u64 acc[8][4];
    #pragma unroll
    for (int a = 0; a < 8; a++)
        #pragma unroll
        for (int b = 0; b < 4; b++) acc[a][b] = 0ull;
    float z2e[8] = {0,0,0,0,0,0,0,0}, z2o[8] = {0,0,0,0,0,0,0,0};

    const float4* Vf4 = (const float4*)Vb;
    float4* Sf4 = (float4*)S;

    // prefetch first V key-pair: keys sk + 2*kh, +1
    float4 va = Vf4[(size_t)(sk + 2 * kh) * 16 + dlane];
    float4 vb = Vf4[(size_t)(sk + 2 * kh + 1) * 16 + dlane];

    // convert one qp row of group G (f4 range [G*32, G*32+32) of the stripe)
#define CONVQP(G, QP)                                                        \
    {                                                                        \
        const float2 cc = *(const float2*)&c2s[2 * (QP)];                    \
        float4* p = Sf4 + (size_t)(QP) * PITCHF4 + wb128 + (G) * 32 + lane;  \
        float4 x = *p;                                                       \
        x.x = ex2f(x.x * cc.x);                                              \
        x.y = ex2f(x.y * cc.y);                                              \
        x.z = ex2f(x.z * cc.x);                                              \
        x.w = ex2f(x.w * cc.y);                                              \
        z2e[(QP)] += x.x + x.z;                                              \
        z2o[(QP)] += x.y + x.w;                                              \
        *p = x;                                                              \
    }

#define MMASTEP(G, S16)                                                      \
    {                                                                        \
        const int s = (G) * 16 + (S16);                                      \
        u64 dA0 = pk2(va.x, va.x), dA1 = pk2(va.y, va.y);                    \
        u64 dA2 = pk2(va.z, va.z), dA3 = pk2(va.w, va.w);                    \
        u64 dB0 = pk2(vb.x, vb.x), dB1 = pk2(vb.y, vb.y);                    \
        u64 dB2 = pk2(vb.z, vb.z), dB3 = pk2(vb.w, vb.w);                    \
        if (s + 1 < 64) {                                                    \
            const int kn = sk + 4 * (s + 1) + 2 * kh;                        \
            va = Vf4[(size_t)kn * 16 + dlane];                               \
            vb = Vf4[(size_t)(kn + 1) * 16 + dlane];                         \
        }                                                                    \
        const int f4o = wb128 + 2 * s + kh;                                  \
        _Pragma("unroll")                                                    \
        for (int qp = 0; qp < 8; qp++) {                                     \
            ulonglong2 pp = *(const ulonglong2*)(Sf4 + (size_t)qp * PITCHF4 + f4o); \
            ffma2(acc[qp][0], pp.x, dA0);                                    \
            ffma2(acc[qp][1], pp.x, dA1);                                    \
            ffma2(acc[qp][2], pp.x, dA2);                                    \
            ffma2(acc[qp][3], pp.x, dA3);                                    \
            ffma2(acc[qp][0], pp.y, dB0);                                    \
            ffma2(acc[qp][1], pp.y, dB1);                                    \
            ffma2(acc[qp][2], pp.y, dB2);                                    \
            ffma2(acc[qp][3], pp.y, dB3);                                    \
        }                                                                    \
    }

    // group 0 convert (serial prologue)
    #pragma unroll
    for (int qp = 0; qp < 8; qp++) CONVQP(0, qp);
    __syncwarp();

    // groups 0..2: MMA(g) with conv(g+1) interleaved (disjoint S regions)
    for (int g = 0; g < 3; g++) {
        #pragma unroll
        for (int s16 = 0; s16 < 16; s16++) {
            MMASTEP(g, s16);
            if ((s16 & 1) == 0) {
                const int qp = s16 >> 1;
                switch (qp) {   // constant register indices for z2e/z2o
                    case 0: CONVQP(g + 1, 0); break;
                    case 1: CONVQP(g + 1, 1); break;
                    case 2: CONVQP(g + 1, 2); break;
                    case 3: CONVQP(g + 1, 3); break;
                    case 4: CONVQP(g + 1, 4); break;
                    case 5: CONVQP(g + 1, 5); break;
                    case 6: CONVQP(g + 1, 6); break;
                    case 7: CONVQP(g + 1, 7); break;
                }
            }
        }
        __syncwarp();         // conv(g+1) complete before MMA(g+1) reads it
    }
    // group 3: plain MMA
    #pragma unroll
    for (int s16 = 0; s16 < 16; s16++) MMASTEP(3, s16);

    // ---- Z2 stripe partials: full-warp reduce per row ----
    #pragma unroll
    for (int qp = 0; qp < 8; qp++) {
        float ve = z2e[qp], vo = z2o[qp];
        #pragma unroll
        for (int o = 16; o > 0; o >>= 1) {
            ve += __shfl_xor_sync(0xffffffffu, ve, o);
            vo += __shfl_xor_sync(0xffffffffu, vo, o);
        }
        if (lane == 0) {
            zscr2[warp * 16 + 2 * qp]     = ve;
            zscr2[warp * 16 + 2 * qp + 1] = vo;
        }
    }

    // ---- cross-(warp,half) reduction through Kt: 16 segments ----
    float* scratch = Kt;                   // [16 seg][16 q][64 d]
    const int seg = warp * 2 + kh;
    #pragma unroll
    for (int qp = 0; qp < 8; qp++) {
        float l0, h0, l1, h1, l2, h2, l3, h3;
        upk2(acc[qp][0], l0, h0);
        upk2(acc[qp][1], l1, h1);
        upk2(acc[qp][2], l2, h2);
        upk2(acc[qp][3], l3, h3);
        *(float4*)&scratch[((seg * MQ + 2 * qp) * 64) + dlane * 4] =
            make_float4(l0, l1, l2, l3);
        *(float4*)&scratch[((seg * MQ + 2 * qp + 1) * 64) + dlane * 4] =
            make_float4(h0, h1, h2, h3);
    }
    __syncthreads();

    #pragma unroll
    for (int e = tid; e < MQ * DIM; e += THREADS) {
        const int q = e >> 6, d = e & 63;
        float r = 0.f, z2 = 0.f;
        #pragma unroll
        for (int sg = 0; sg < 16; sg++)
            r += scratch[(sg * MQ + q) * 64 + d];
        #pragma unroll
        for (int w = 0; w < 8; w++)
            z2 += zscr2[w * 16 + q];
        Ob[(size_t)q * DIM + d] = __fdividef(r, z2);
    }
}

extern "C" void kernel_launch(void* const* d_in, const int* in_sizes, int n_in,
                              void* d_out, int out_size)
{
    const float* q     = (const float*)d_in[0];
    const float* k     = (const float*)d_in[1];
    const float* v     = (const float*)d_in[2];
    const float* scale = (const float*)d_in[3];
    float* out = (float*)d_out;

    cudaFuncSetAttribute(dsmax_attn_kernel,
                         cudaFuncAttributeMaxDynamicSharedMemorySize, SMEM_BYTES);

    dim3 grid(32 * NBLK_Q);   // (B*H) * query-blocks = 4096
    dsmax_attn_kernel<<<grid, THREADS, SMEM_BYTES>>>(q, k, v, scale, out);
}

// round 16
// speedup vs baseline: 1.5950x; 1.5950x over previous
#include <cuda_runtime.h>

// Double-softmax attention, fp32. B=4,H=8,N=2048,D=64.
//   L = Q K^T * scale ; mask = softmax(2L) ; attn = softmax(L*mask) ; O = attn V
// One CTA = 16 query rows of one (b,h), 256 threads, warp-local staging.
// P1: register-prefetched 256-key K chunks, t = L*exp(2L), Z1 folded.
// S panel: S2[qpair][key][2], pitch 4100 floats -> P3 LDS.128 = 2 FFMA2 P-pairs.
// P3: per-group exp2 convert + O = P V (proven R13 schedule), early V prefetch.

#define NKEYS   2048
#define DIM     64
#define MQ      16
#define CHUNK   256
#define NCHUNK  8
#define THREADS 256
#define NBLK_Q  128

#define PITCH2    4100                 // S2 row pitch in floats (16B bank stagger)
#define PITCHF4   (PITCH2 / 4)         // 1025
#define S_FLOATS  (8 * PITCH2)         // 32800
#define KT_FLOATS (CHUNK * DIM)        // 16384 (K tile; P3 scratch 16 segs)
#define QS_FLOATS (MQ * DIM)           // 1024
#define SMEM_FLOATS (S_FLOATS + KT_FLOATS + QS_FLOATS + 128 + 16 + 128)
#define SMEM_BYTES  (SMEM_FLOATS * 4)  // ~202 KB

typedef unsigned long long u64;

__device__ __forceinline__ u64 pk2(float lo, float hi) {
    u64 r; asm("mov.b64 %0,{%1,%2};" : "=l"(r) : "f"(lo), "f"(hi)); return r;
}
__device__ __forceinline__ void upk2(u64 a, float& lo, float& hi) {
    asm("mov.b64 {%0,%1},%2;" : "=f"(lo), "=f"(hi) : "l"(a));
}
__device__ __forceinline__ void ffma2(u64& d, u64 a, u64 b) {
    asm("fma.rn.f32x2 %0,%1,%2,%0;" : "+l"(d) : "l"(a), "l"(b));
}
__device__ __forceinline__ float ex2f(float x) {
    float r; asm("ex2.approx.f32 %0,%1;" : "=f"(r) : "f"(x)); return r;
}

__global__ __launch_bounds__(THREADS, 1)
void dsmax_attn_kernel(const float* __restrict__ Q,
                       const float* __restrict__ K,
                       const float* __restrict__ V,
                       const float* __restrict__ scalep,
                       float* __restrict__ O)
{
    extern __shared__ float smem[];
    float* S     = smem;                      // S2: [8 qp][PITCH2]  t -> P'
    float* Kt    = S + S_FLOATS;              // [CHUNK][DIM] swizzled K / P3 scratch
    float* Qs    = Kt + KT_FLOATS;            // [MQ][DIM] swizzled Q
    float* zscr  = Qs + QS_FLOATS;            // [8 warps][16 rows] Z1 partials
    float* c2s   = zscr + 128;                // [16] log2e / Z1
    float* zscr2 = c2s + 16;                  // [8 warps][16 rows] Z2 partials

    const int tid  = threadIdx.x;
    const int warp = tid >> 5, lane = tid & 31;
    const int bh   = blockIdx.x >> 7;
    const int qb   = (blockIdx.x & (NBLK_Q - 1)) * MQ;
    const float scale = *scalep;

    const float* Qb = Q + ((size_t)bh * NKEYS + qb) * DIM;
    const float* Kb = K + (size_t)bh * NKEYS * DIM;
    const float* Vb = V + (size_t)bh * NKEYS * DIM;
    float*       Ob = O + ((size_t)bh * NKEYS + qb) * DIM;

    // ---- stage Q swizzled: col16 = d4 ^ ((q>>2)&3) ----
    {
        const int q = tid >> 4, d4 = tid & 15;
        *(float4*)&Qs[q * DIM + ((d4 ^ ((q >> 2) & 3)) << 2)] = ((const float4*)Qb)[tid];
    }

    // ---- warp-local K prefetch: warp w owns keys [32w, 32w+32) of each chunk ----
    float4 pf[16];
    const int lhi = lane >> 4;          // key parity within pair
    const int ld4 = lane & 15;          // float4 column within key row
#define LDGK(C)                                                               \
    {                                                                         \
        const float4* src = (const float4*)(Kb + (size_t)(C) * CHUNK * DIM);  \
        _Pragma("unroll")                                                     \
        for (int i = 0; i < 16; i++)                                          \
            pf[i] = src[(size_t)(32 * warp + 2 * i + lhi) * 16 + ld4];        \
    }
    LDGK(0);
    __syncthreads();   // Qs visible to everyone

    // ================= Phase 1: t = L*exp(2L), Z1 partials =================
    // Thread keys: {32w + l7 + 8j, j=0..3}; rows 4qg..4qg+3.
    const int l7 = lane & 7;
    const int qg = (lane >> 3) & 3;
    float z1p[4] = {0.f, 0.f, 0.f, 0.f};

    for (int c = 0; c < NCHUNK; c++) {
        // commit own slice, swizzle col16 = ld4 ^ (key & 7)
        #pragma unroll
        for (int i = 0; i < 16; i++) {
            const int key = 32 * warp + 2 * i + lhi;
            *(float4*)&Kt[key * DIM + ((ld4 ^ ((2 * i + lhi) & 7)) << 2)] = pf[i];
        }
        __syncwarp();                 // slice visible to own warp
        if (c + 1 < NCHUNK) LDGK(c + 1);

        u64 acc[4][4];   // [jq][j]
        #pragma unroll
        for (int a = 0; a < 4; a++)
            #pragma unroll
            for (int b = 0; b < 4; b++) acc[a][b] = 0ull;

        const float* kr0 = Kt + (32 * warp + l7) * DIM;
        #pragma unroll
        for (int d4 = 0; d4 < 16; d4++) {
            const int kco = (d4 ^ l7) << 2;
            ulonglong2 kv[4];
            #pragma unroll
            for (int j = 0; j < 4; j++)
                kv[j] = *(const ulonglong2*)(kr0 + (8 * j) * DIM + kco);
            const int qco = (d4 ^ qg) << 2;
            #pragma unroll
            for (int jq = 0; jq < 4; jq++) {
                ulonglong2 qv = *(const ulonglong2*)(Qs + (4 * qg + jq) * DIM + qco);
                #pragma unroll
                for (int j = 0; j < 4; j++) {
                    ffma2(acc[jq][j], qv.x, kv[j].x);
                    ffma2(acc[jq][j], qv.y, kv[j].y);
                }
            }
        }

        // epilogue: t = L*exp(2L); q-pair float2s into S2
        float tmat[4][4];
        #pragma unroll
        for (int jq = 0; jq < 4; jq++) {
            #pragma unroll
            for (int j = 0; j < 4; j++) {
                float lo, hi; upk2(acc[jq][j], lo, hi);
                float L  = (lo + hi) * scale;
                float e2 = __expf(2.0f * L);
                z1p[jq] += e2;
                tmat[jq][j] = L * e2;
            }
        }
        #pragma unroll
        for (int p01 = 0; p01 < 2; p01++) {
            const int qp = 2 * qg + p01;
            #pragma unroll
            for (int j = 0; j < 4; j++) {
                const int gk = c * CHUNK + 32 * warp + l7 + 8 * j;
                *(float2*)&S[(size_t)qp * PITCH2 + gk * 2] =
                    make_float2(tmat[2 * p01][j], tmat[2 * p01 + 1][j]);
            }
        }
        __syncwarp();                 // own warp done reading slice before next commit
    }

    // ---- early V prefetch: first key-pair of warp's stripe (hides L2 latency
    //      under the Z1 reduction + barriers below) ----
    const int dlane = lane & 15;
    const int kh    = lane >> 4;
    const int sk    = warp * 256;
    const float4* Vf4 = (const float4*)Vb;
    float4 va = Vf4[(size_t)(sk + 2 * kh) * 16 + dlane];
    float4 vb = Vf4[(size_t)(sk + 2 * kh + 1) * 16 + dlane];

    // ---- Z1 reduce: over the 8 l7 lanes, then across warps ----
    #pragma unroll
    for (int jq = 0; jq < 4; jq++) {
        float v = z1p[jq];
        v += __shfl_xor_sync(0xffffffffu, v, 1);
        v += __shfl_xor_sync(0xffffffffu, v, 2);
        v += __shfl_xor_sync(0xffffffffu, v, 4);
        if (l7 == 0) zscr[warp * 16 + qg * 4 + jq] = v;   // slot == row q
    }
    __syncthreads();
    if (tid < 16) {
        float z1 = 0.f;
        #pragma unroll
        for (int w = 0; w < 8; w++) z1 += zscr[w * 16 + tid];
        c2s[tid] = 1.4426950408889634f / z1;      // log2e / Z1
    }
    __syncthreads();

    // ================= Phase 3: warp-local convert + O = P' V =================
    // Warp w owns stripe keys [256w, +256). Lanes: 16 d-lanes x 2 key-halves.
    const int wb128 = warp * 128;               // stripe base in f4 units per qp row

    u64 acc[8][4];
    #pragma unroll
    for (int a = 0; a < 8; a++)
        #pragma unroll
        for (int b = 0; b < 4; b++) acc[a][b] = 0ull;
    float z2e[8] = {0,0,0,0,0,0,0,0}, z2o[8] = {0,0,0,0,0,0,0,0};

    float4* Sf4 = (float4*)S;

    for (int g = 0; g < 4; g++) {
        // convert stripe keys [g*64, g*64+64) for all 8 qp rows (warp-local)
        #pragma unroll
        for (int qp = 0; qp < 8; qp++) {
            const float2 cc = *(const float2*)&c2s[2 * qp];
            float4* p = Sf4 + (size_t)qp * PITCHF4 + wb128 + g * 32 + lane;
            float4 x = *p;
            x.x = ex2f(x.x * cc.x);
            x.y = ex2f(x.y * cc.y);
            x.z = ex2f(x.z * cc.x);
            x.w = ex2f(x.w * cc.y);
            z2e[qp] += x.x + x.z;
            z2o[qp] += x.y + x.w;
            *p = x;
        }
        __syncwarp();                 // group converted, visible to own warp

        #pragma unroll 4
        for (int s16 = 0; s16 < 16; s16++) {
            const int s = g * 16 + s16;
            // dup-pack current V key-pair
            u64 dA0 = pk2(va.x, va.x), dA1 = pk2(va.y, va.y);
            u64 dA2 = pk2(va.z, va.z), dA3 = pk2(va.w, va.w);
            u64 dB0 = pk2(vb.x, vb.x), dB1 = pk2(vb.y, vb.y);
            u64 dB2 = pk2(vb.z, vb.z), dB3 = pk2(vb.w, vb.w);
            // prefetch next key-pair
            if (s + 1 < 64) {
                const int kn = sk + 4 * (s + 1) + 2 * kh;
                va = Vf4[(size_t)kn * 16 + dlane];
                vb = Vf4[(size_t)(kn + 1) * 16 + dlane];
            }
            const int f4o = wb128 + 2 * s + kh;
            #pragma unroll
            for (int qp = 0; qp < 8; qp++) {
                ulonglong2 pp = *(const ulonglong2*)(Sf4 + (size_t)qp * PITCHF4 + f4o);
                ffma2(acc[qp][0], pp.x, dA0);
                ffma2(acc[qp][1], pp.x, dA1);
                ffma2(acc[qp][2], pp.x, dA2);
                ffma2(acc[qp][3], pp.x, dA3);
                ffma2(acc[qp][0], pp.y, dB0);
                ffma2(acc[qp][1], pp.y, dB1);
                ffma2(acc[qp][2], pp.y, dB2);
                ffma2(acc[qp][3], pp.y, dB3);
            }
        }
    }

    // ---- Z2 stripe partials: full-warp reduce per row ----
    #pragma unroll
    for (int qp = 0; qp < 8; qp++) {
        float ve = z2e[qp], vo = z2o[qp];
        #pragma unroll
        for (int o = 16; o > 0; o >>= 1) {
            ve += __shfl_xor_sync(0xffffffffu, ve, o);
            vo += __shfl_xor_sync(0xffffffffu, vo, o);
        }
        if (lane == 0) {
            zscr2[warp * 16 + 2 * qp]     = ve;
            zscr2[warp * 16 + 2 * qp + 1] = vo;
        }
    }

    // ---- cross-(warp,half) reduction through Kt: 16 segments ----
    float* scratch = Kt;                   // [16 seg][16 q][64 d]
    const int seg = warp * 2 + kh;
    #pragma unroll
    for (int qp = 0; qp < 8; qp++) {
        float l0, h0, l1, h1, l2, h2, l3, h3;
        upk2(acc[qp][0], l0, h0);
        upk2(acc[qp][1], l1, h1);
        upk2(acc[qp][2], l2, h2);
        upk2(acc[qp][3], l3, h3);
        *(float4*)&scratch[((seg * MQ + 2 * qp) * 64) + dlane * 4] =
            make_float4(l0, l1, l2, l3);
        *(float4*)&scratch[((seg * MQ + 2 * qp + 1) * 64) + dlane * 4] =
            make_float4(h0, h1, h2, h3);
    }
    __syncthreads();

    // ---- final: float4 reduce + store (one f4 per thread) ----
    {
        const int e  = tid;                 // 256 = MQ*DIM/4 outputs
        const int q  = e >> 4;
        const int f4 = e & 15;
        float4 r = make_float4(0.f, 0.f, 0.f, 0.f);
        #pragma unroll
        for (int sg = 0; sg < 16; sg++) {
            const float4 s4 = *(const float4*)&scratch[(sg * MQ + q) * 64 + f4 * 4];
            r.x += s4.x; r.y += s4.y; r.z += s4.z; r.w += s4.w;
        }
        float z2 = 0.f;
        #pragma unroll
        for (int w = 0; w < 8; w++)
            z2 += zscr2[w * 16 + q];
        const float iz = __fdividef(1.0f, z2);
        r.x *= iz; r.y *= iz; r.z *= iz; r.w *= iz;
        *(float4*)&Ob[(size_t)q * DIM + f4 * 4] = r;
    }
}

extern "C" void kernel_launch(void* const* d_in, const int* in_sizes, int n_in,
                              void* d_out, int out_size)
{
    const float* q     = (const float*)d_in[0];
    const float* k     = (const float*)d_in[1];
    const float* v     = (const float*)d_in[2];
    const float* scale = (const float*)d_in[3];
    float* out = (float*)d_out;

    cudaFuncSetAttribute(dsmax_attn_kernel,
                         cudaFuncAttributeMaxDynamicSharedMemorySize, SMEM_BYTES);

    dim3 grid(32 * NBLK_Q);   // (B*H) * query-blocks = 4096
    dsmax_attn_kernel<<<grid, THREADS, SMEM_BYTES>>>(q, k, v, scale, out);
}